// round 15
// baseline (speedup 1.0000x reference)
#include <cuda_runtime.h>
#include <math.h>

// Problem constants (match reference)
#define BB 8
#define HH 256
#define WW 256
#define RPW 4                       // output rows per warp tile
#define DRW 8                       // decoded rows per warp (RPW + 2*2)
#define WPB 8                       // warps per block
#define NBLK 512                    // 4096 warp-tiles / 8
#define PAD_PAIR 0x00100010u        // (16,16): >9 -> can only force fallback

typedef unsigned u32;

// ---------------------------------------------------------------------------
// Scratch (device globals — no allocation allowed)
// ---------------------------------------------------------------------------
__device__ double d_partials[NBLK][4];   // {sum p*dist, sum p*t, sum p*p, sum t}
__device__ int g_fin;                    // finalize election counter (self-resetting)

// Exact squared distance to nearest set (inv=false) / clear (inv=true) bit in
// a 256-bit row mask (1e10 if none == reference INF). Fallback-only.
__device__ __forceinline__ float exact_dist2(const u32* m, int i, bool inv) {
    const int wi = i >> 5, bi = i & 31;
    const u32 mw = inv ? ~m[wi] : m[wi];
    const u32 lowmask = (2u << bi) - 1u;
    const u32 himask  = ~((1u << bi) - 1u);
    u32 wl = mw & lowmask;
    int dl = 100000;
    if (wl) dl = bi - (31 - __clz(wl));
    else {
        for (int k = wi - 1; k >= 0; --k) {
            const u32 mk = inv ? ~m[k] : m[k];
            if (mk) { dl = i - (k * 32 + 31 - __clz(mk)); break; }
        }
    }
    u32 wr = mw & himask;
    int dr = 100000;
    if (wr) dr = (__ffs(wr) - 1) - bi;
    else {
        for (int k = wi + 1; k < 8; ++k) {
            const u32 mk = inv ? ~m[k] : m[k];
            if (mk) { dr = (k * 32 + __ffs(mk) - 1) - i; break; }
        }
    }
    const int d = min(dl, dr);
    return (d >= 1000) ? 1e10f : (float)(d * d);
}

// ---------------------------------------------------------------------------
// Warp-autonomous kernel: each warp owns a 32-col x 4-row tile. Two ballots
// per row give a 38-col bit strip; lane decode is one funnel-shift + clz.
// No block barriers on the fast path (only the final 8-warp combine).
// ---------------------------------------------------------------------------
__global__ __launch_bounds__(WPB * 32) void fused(const float* __restrict__ pred,
                                                  const float* __restrict__ target,
                                                  const int* __restrict__ fl_ptr,
                                                  float* __restrict__ out) {
    const int blk  = blockIdx.x;
    const int tid  = threadIdx.x;
    const int warp = tid >> 5;
    const int lane = tid & 31;

    const int gw   = blk * WPB + warp;     // global warp-tile id [0,4096)
    const int seg  = gw & 7;               // 32-column segment
    const int rt   = (gw >> 3) & 63;       // row tile
    const int b    = gw >> 9;              // image
    const int y0   = rt * RPW;
    const int base = b * HH * WW;
    const int x    = seg * 32 + lane;      // my column

    __shared__ u32   swp[WPB][8];          // warp-private fallback scratch
    __shared__ float rsf[WPB][4];
    __shared__ double fg[8][2];
    __shared__ int s_last;

    // ---- hoisted loads ------------------------------------------------------
    const int fl = *fl_ptr;
    float pv[RPW];
#pragma unroll
    for (int il = 0; il < RPW; ++il)
        pv[il] = pred[base + (y0 + il) * WW + x];

    // ---- per-row: 2 ballots -> 7-bit window -> packed pair (register-only) --
    const int c0 = seg * 32 - 3 + lane;            // ballot0 column
    const int c1 = seg * 32 + 29 + lane;           // ballot1 column
    const int c0c = min(max(c0, 0), WW - 1);
    const int c1c = min(c1, WW - 1);
    u32 vm = 0x7Fu;                                // class-0 valid mask
    if (x < 3)   vm &= (0x7Fu << (3 - x));
    if (x > 252) vm &= (0x7Fu >> (x - 252));

    u32 R[DRW];
    int tb[RPW];
#pragma unroll
    for (int j = 0; j < DRW; ++j) {
        const int ry  = y0 - 2 + j;
        const int ryc = min(max(ry, 0), HH - 1);
        const float t0 = target[base + ryc * WW + c0c];
        u32 bal0 = __ballot_sync(0xffffffffu, t0 > 0.5f);
        const float t1 = target[base + ryc * WW + c1c];
        u32 bal1 = __ballot_sync(0xffffffffu, t1 > 0.5f);
        if (seg == 0) bal0 &= 0xFFFFFFF8u;          // cols <0 are zero
        if (seg == 7) bal1 &= 0x7u;                 // cols >255 are zero
        const u32 win = __funnelshift_r(bal0, bal1, lane) & 0x7Fu; // cols x-3..x+3
        if (j >= 2 && j < 2 + RPW) tb[j - 2] = (win >> 3) & 1u;
        // nearest 1 (center bit 3)
        u32 rv = __brev(win) >> 25;
        const int d1 = min(__clz(win & 0xFu) - 28, __clz(rv & 0xFu) - 28);
        // nearest 0 (complement within valid bits)
        const u32 w0 = (win ^ 0x7Fu) & vm;
        rv = __brev(w0) >> 25;
        const int d0 = min(__clz(w0 & 0xFu) - 28, __clz(rv & 0xFu) - 28);
        const u32 q1 = __byte_perm(0x09040100u, 0x10u, d1);
        const u32 q0 = __byte_perm(0x09040100u, 0x10u, d0);
        const u32 pair = q1 | (q0 << 16);
        R[j] = ((unsigned)ry < (unsigned)HH) ? pair : PAD_PAIR;
    }

    // ---- packed windowed column min-plus (K=2) ------------------------------
    const u32 C1 = 0x00010001u;
    const u32 C4 = 0x00040004u;
    u32 mp[RPW];
#pragma unroll
    for (int il = 0; il < RPW; ++il) {
        u32 v = R[il + 2];
        v = __vminu2(v, __vminu2(R[il + 1], R[il + 3]) + C1);
        v = __vminu2(v, __vminu2(R[il],     R[il + 4]) + C4);
        mp[il] = v;
    }

    // ---- exactness (warp-local): valid iff every windowed min <= 9 ----------
    const u32 mx2 = __vmaxu2(__vmaxu2(mp[0], mp[1]), __vmaxu2(mp[2], mp[3]));
    const u32 mxv = max(mx2 & 0xFFFFu, mx2 >> 16);
    float msel[RPW];
    const int need_full = __any_sync(0xffffffffu, (int)(mxv > 9u));
    if (!need_full) {
#pragma unroll
        for (int il = 0; il < RPW; ++il)
            msel[il] = (float)(tb[il] ? (mp[il] >> 16) : (mp[il] & 0xFFFFu));
    } else {
        // Warp-private exact fallback (deterministic; ~never executes).
        float mf[RPW];
#pragma unroll
        for (int il = 0; il < RPW; ++il) mf[il] = 3.0e38f;
        for (int r = 0; r < HH; ++r) {
#pragma unroll
            for (int sg = 0; sg < 8; ++sg) {
                const float t = target[base + r * WW + sg * 32 + lane];
                const u32 bal = __ballot_sync(0xffffffffu, t > 0.5f);
                if (lane == 0) swp[warp][sg] = bal;
            }
            __syncwarp();
            const float d1 = exact_dist2(swp[warp], x, false);
            const float d0 = exact_dist2(swp[warp], x, true);
            __syncwarp();
#pragma unroll
            for (int il = 0; il < RPW; ++il) {
                const int dy = y0 + il - r;
                const float dv = tb[il] ? d0 : d1;
                mf[il] = fminf(mf[il], dv + (float)(dy * dy));
            }
        }
#pragma unroll
        for (int il = 0; il < RPW; ++il) msel[il] = mf[il];
    }

    // ---- epilogue: sigmoid + partial sums -----------------------------------
    float s_pd = 0.0f, s_pt = 0.0f, s_pp = 0.0f;
    int s_tt = 0;
#pragma unroll
    for (int il = 0; il < RPW; ++il) {
        float p = pv[il];
        if (fl) p = __fdividef(1.0f, 1.0f + __expf(-p));
        s_pd += p * sqrtf(msel[il]);
        s_pp += p * p;
        if (tb[il]) { s_pt += p; s_tt += 1; }
    }
    float s_ttf = (float)s_tt;

#pragma unroll
    for (int off = 16; off > 0; off >>= 1) {
        s_pd  += __shfl_down_sync(0xffffffffu, s_pd,  off);
        s_pt  += __shfl_down_sync(0xffffffffu, s_pt,  off);
        s_pp  += __shfl_down_sync(0xffffffffu, s_pp,  off);
        s_ttf += __shfl_down_sync(0xffffffffu, s_ttf, off);
    }
    if (lane == 0) {
        rsf[warp][0] = s_pd; rsf[warp][1] = s_pt;
        rsf[warp][2] = s_pp; rsf[warp][3] = s_ttf;
    }
    __syncthreads();

    if (warp == 0) {
        float a0 = 0.f, a1 = 0.f, a2 = 0.f, a3 = 0.f;
        if (lane < WPB) {
            a0 = rsf[lane][0]; a1 = rsf[lane][1];
            a2 = rsf[lane][2]; a3 = rsf[lane][3];
        }
#pragma unroll
        for (int off = 4; off > 0; off >>= 1) {
            a0 += __shfl_down_sync(0xffffffffu, a0, off);
            a1 += __shfl_down_sync(0xffffffffu, a1, off);
            a2 += __shfl_down_sync(0xffffffffu, a2, off);
            a3 += __shfl_down_sync(0xffffffffu, a3, off);
        }
        if (lane == 0) {
            d_partials[blk][0] = (double)a0; d_partials[blk][1] = (double)a1;
            d_partials[blk][2] = (double)a2; d_partials[blk][3] = (double)a3;
            __threadfence();
            const int old = atomicAdd(&g_fin, 1);
            s_last = (old == NBLK - 1);
        }
    }
    __syncthreads();
    if (!s_last) return;

    // ---- last block: deterministic finalize ---------------------------------
    __threadfence();
    if (warp < 8) {
        const int img = warp;              // blocks [img*64, (img+1)*64)
        const int s = img * 64 + lane;
        double v0 = d_partials[s][0] + d_partials[s + 32][0];
        double v1 = d_partials[s][1] + d_partials[s + 32][1];
        double v2 = d_partials[s][2] + d_partials[s + 32][2];
        double v3 = d_partials[s][3] + d_partials[s + 32][3];
#pragma unroll
        for (int off = 16; off > 0; off >>= 1) {
            v0 += __shfl_down_sync(0xffffffffu, v0, off);
            v1 += __shfl_down_sync(0xffffffffu, v1, off);
            v2 += __shfl_down_sync(0xffffffffu, v2, off);
            v3 += __shfl_down_sync(0xffffffffu, v3, off);
        }
        if (lane == 0) {
            const double eps = 1e-6;
            fg[img][0] = v0;                                       // boundary sum
            fg[img][1] = 1.0 - (2.0 * v1 + eps) / (v2 + v3 + eps); // dice term
        }
    }
    __syncthreads();
    if (tid == 0) {
        double bl = 0.0, dl = 0.0;
#pragma unroll
        for (int i = 0; i < BB; ++i) { bl += fg[i][0]; dl += fg[i][1]; }
        dl /= (double)BB;
        bl /= (double)(BB * HH * WW);
        out[0] = (float)(dl + bl);  // ALPHA = BETA = 1
        g_fin = 0;                  // reset for next (graph) replay
        __threadfence();
    }
}

// ---------------------------------------------------------------------------
extern "C" void kernel_launch(void* const* d_in, const int* in_sizes, int n_in,
                              void* d_out, int out_size) {
    const float* pred   = (const float*)d_in[0];
    const float* target = (const float*)d_in[1];
    const int*   fl     = (const int*)d_in[2];
    float* out = (float*)d_out;

    fused<<<NBLK, WPB * 32>>>(pred, target, fl, out);
}

// round 16
// speedup vs baseline: 1.1029x; 1.1029x over previous
#include <cuda_runtime.h>
#include <math.h>

// Problem constants (match reference)
#define BB 8
#define HH 256
#define WW 256
#define RR 8                        // output rows per block
#define NG 2                        // row groups (thread split)
#define RPG (RR / NG)               // output rows per thread (4)
#define KW 2                        // column window radius (exactness-checked)
#define DR (RR + 2 * KW)            // decoded rows per block (12)
#define NBLK (BB * (HH / RR))       // 256 blocks
#define NTH  (WW * NG)              // 512 threads
#define PAD_PAIR 0x00100010u        // (16,16): >9 -> can only force fallback

typedef unsigned u32;

// ---------------------------------------------------------------------------
// Scratch (device globals — no allocation allowed)
// ---------------------------------------------------------------------------
__device__ double d_partials[NBLK][4];   // {sum p*dist, sum p*t, sum p*p, sum t}
__device__ int g_fin;                    // finalize election counter (self-resetting)

// Exact squared distance to nearest set (inv=false) / clear (inv=true) bit in
// a 256-bit row mask (1e10 if none == reference INF). Fallback-only.
__device__ __forceinline__ float exact_dist2(const u32* m, int i, bool inv) {
    const int wi = i >> 5, bi = i & 31;
    const u32 mw = inv ? ~m[wi] : m[wi];
    const u32 lowmask = (2u << bi) - 1u;
    const u32 himask  = ~((1u << bi) - 1u);
    u32 wl = mw & lowmask;
    int dl = 100000;
    if (wl) dl = bi - (31 - __clz(wl));
    else {
        for (int k = wi - 1; k >= 0; --k) {
            const u32 mk = inv ? ~m[k] : m[k];
            if (mk) { dl = i - (k * 32 + 31 - __clz(mk)); break; }
        }
    }
    u32 wr = mw & himask;
    int dr = 100000;
    if (wr) dr = (__ffs(wr) - 1) - bi;
    else {
        for (int k = wi + 1; k < 8; ++k) {
            const u32 mk = inv ? ~m[k] : m[k];
            if (mk) { dr = (k * 32 + __ffs(mk) - 1) - i; break; }
        }
    }
    const int d = min(dl, dr);
    return (d >= 1000) ? 1e10f : (float)(d * d);
}

// ---------------------------------------------------------------------------
// 512-thread blocks: thread = (column x, row-group g). Block = 8 output rows
// of one image. K=2 window. JOINT-CLASS decode: center class bit selects the
// single distance computation (the other class distance is 0 by definition);
// packed u16x2 pairs; 5-tap packed min-plus; exact iff result <= 9 else
// exact fallback; popc t-count; last-block deterministic finalize.
// ---------------------------------------------------------------------------
__global__ __launch_bounds__(NTH) void fused(const float* __restrict__ pred,
                                             const float* __restrict__ target,
                                             const int* __restrict__ fl_ptr,
                                             float* __restrict__ out) {
    const int blk  = blockIdx.x;
    const int tid  = threadIdx.x;
    const int warp = tid >> 5;             // 0..15
    const int lane = tid & 31;
    const int x    = tid & 255;            // column
    const int g    = tid >> 8;             // row group 0/1

    const int b  = blk >> 5;               // image  (32 blocks per image)
    const int y0 = (blk & 31) * RR;        // first output row
    const int base = b * HH * WW;

    __shared__ u32 sbits[DR][10];          // zero-padded bit rows: [0]=[9]=0
    __shared__ u32 sfull[HH][8];           // fallback-only: full-image bit rows
    __shared__ float rs[16][3];
    __shared__ double fg[8][2];
    __shared__ int s_last;

    // ---- Hoisted global loads ----------------------------------------------
    const int fl = *fl_ptr;
    float pv[RPG];
#pragma unroll
    for (int il = 0; il < RPG; ++il)
        pv[il] = pred[base + (y0 + g * RPG + il) * WW + x];

    // zero the pad words
    if (tid < DR * 2) sbits[tid >> 1][(tid & 1) * 9] = 0u;

    // ---- ballots: 96 warp-tasks (12 rows x 8 segments), clamped loads ------
#pragma unroll
    for (int it = 0; it < 6; ++it) {
        const int task = warp + 16 * it;   // 0..95
        const int dr  = task >> 3;
        const int seg = task & 7;
        const int ry  = min(max(y0 - KW + dr, 0), HH - 1);   // clamped
        const float t = target[base + ry * WW + (seg << 5) + lane];
        const u32 bal = __ballot_sync(0xffffffffu, t > 0.5f);
        if (lane == 0) sbits[dr][1 + seg] = bal;
    }
    __syncthreads();

    // ---- joint-class register decode: 8 rows/thread -------------------------
    const int sh   = x - 3;
    const int wiw1 = (sh >> 5) + 1;        // arithmetic shift: x<3 -> 0 (pad)
    const int shr  = sh & 31;
    u32 vm = 0x7Fu;                        // valid-bit mask (for class-0 side)
    if (x < 3)   vm &= (0x7Fu << (3 - x));
    if (x > 252) vm &= (0x7Fu >> (x - 252));

    u32 R[RPG + 2 * KW];
    int tb[RPG];
#pragma unroll
    for (int k = 0; k < RPG + 2 * KW; ++k) {
        const int dr = g * RPG + k;
        const int ry = y0 - KW + dr;
        const u32 lo = sbits[dr][wiw1];
        const u32 hi = sbits[dr][wiw1 + 1];
        const u32 win = __funnelshift_r(lo, hi, shr) & 0x7Fu;   // OOB bits 0
        const u32 c = (win >> 3) & 1u;                          // center class
        if (k >= KW && k < KW + RPG) tb[k - KW] = (int)c;
        // distance to nearest OPPOSITE bit of the row-center pixel:
        // c=1 -> nearest 0 (complement, masked valid); c=0 -> nearest 1.
        const u32 V  = c ? ((win ^ 0x7Fu) & vm) : win;
        const u32 rv = __brev(V) >> 25;                         // 7-bit reversal
        const int d  = min(__clz(V & 0xFu) - 28, __clz(rv & 0xFu) - 28);
        const u32 q  = __byte_perm(0x09040100u, 0x10u, d);      // d^2 (d<=4)
        const u32 pair = c ? (q << 16) : q;   // (d1^2, d0^2), other half = 0
        R[k] = ((unsigned)ry < (unsigned)HH) ? pair : PAD_PAIR;
    }

    // ---- packed windowed column min-plus (K=2), 4 outputs per thread -------
    const u32 C1 = 0x00010001u;
    const u32 C4 = 0x00040004u;
    u32 mp[RPG];
#pragma unroll
    for (int il = 0; il < RPG; ++il) {
        u32 v = R[il + 2];
        v = __vminu2(v, __vminu2(R[il + 1], R[il + 3]) + C1);
        v = __vminu2(v, __vminu2(R[il],     R[il + 4]) + C4);
        mp[il] = v;
    }

    // ---- exactness check: valid iff every windowed min <= 9 ----------------
    const u32 mx2 = __vmaxu2(__vmaxu2(mp[0], mp[1]), __vmaxu2(mp[2], mp[3]));
    const u32 mxv = max(mx2 & 0xFFFFu, mx2 >> 16);
    float msel[RPG];
    const int need_full = __syncthreads_or((int)(mxv > 9u));
    if (!need_full) {
#pragma unroll
        for (int il = 0; il < RPG; ++il)
            msel[il] = (float)(tb[il] ? (mp[il] >> 16) : (mp[il] & 0xFFFFu));
    } else {
        // Exact full-image float fallback (deterministic; rarely executes).
        for (int it = 0; it < (HH * 8) / 16; ++it) {   // 2048 warp-tasks
            const int task = warp + 16 * it;
            const int r  = task >> 3;
            const int sg = task & 7;
            const float t = target[base + r * WW + (sg << 5) + lane];
            const u32 bal = __ballot_sync(0xffffffffu, t > 0.5f);
            if (lane == 0) sfull[r][sg] = bal;
        }
        __syncthreads();
        float mf[RPG];
#pragma unroll
        for (int il = 0; il < RPG; ++il) mf[il] = 3.0e38f;
        for (int r = 0; r < HH; ++r) {
            const float d1 = exact_dist2(sfull[r], x, false);
            const float d0 = exact_dist2(sfull[r], x, true);
#pragma unroll
            for (int il = 0; il < RPG; ++il) {
                const int dy = y0 + g * RPG + il - r;
                const float dv = tb[il] ? d0 : d1;
                mf[il] = fminf(mf[il], dv + (float)(dy * dy));
            }
        }
#pragma unroll
        for (int il = 0; il < RPG; ++il) msel[il] = mf[il];
    }

    // ---- epilogue: sigmoid + partial sums (t-count via popc in reduce) -----
    float s_pd = 0.0f, s_pt = 0.0f, s_pp = 0.0f;
#pragma unroll
    for (int il = 0; il < RPG; ++il) {
        float p = pv[il];
        if (fl) p = __fdividef(1.0f, 1.0f + __expf(-p));
        s_pd += p * sqrtf(msel[il]);       // dist_map = dist to opposite class
        s_pp += p * p;
        if (tb[il]) s_pt += p;
    }

#pragma unroll
    for (int off = 16; off > 0; off >>= 1) {
        s_pd += __shfl_down_sync(0xffffffffu, s_pd, off);
        s_pt += __shfl_down_sync(0xffffffffu, s_pt, off);
        s_pp += __shfl_down_sync(0xffffffffu, s_pp, off);
    }
    if (lane == 0) {
        rs[warp][0] = s_pd; rs[warp][1] = s_pt; rs[warp][2] = s_pp;
    }
    __syncthreads();

    if (warp == 0) {
        float a0 = 0.f, a1 = 0.f, a2 = 0.f;
        if (lane < 16) {
            a0 = rs[lane][0]; a1 = rs[lane][1]; a2 = rs[lane][2];
        }
        // t-count: popc over the 8 center ballot rows (64 words, 2 per lane)
        int tc = __popc(sbits[KW + (lane >> 3)][1 + (lane & 7)])
               + __popc(sbits[KW + 4 + (lane >> 3)][1 + (lane & 7)]);
        float a3 = (float)tc;
#pragma unroll
        for (int off = 16; off > 0; off >>= 1) {
            a0 += __shfl_down_sync(0xffffffffu, a0, off);
            a1 += __shfl_down_sync(0xffffffffu, a1, off);
            a2 += __shfl_down_sync(0xffffffffu, a2, off);
            a3 += __shfl_down_sync(0xffffffffu, a3, off);
        }
        if (lane == 0) {
            d_partials[blk][0] = (double)a0; d_partials[blk][1] = (double)a1;
            d_partials[blk][2] = (double)a2; d_partials[blk][3] = (double)a3;
            __threadfence();
            const int old = atomicAdd(&g_fin, 1);
            s_last = (old == NBLK - 1);
        }
    }
    __syncthreads();
    if (!s_last) return;

    // ---- last block: deterministic finalize --------------------------------
    __threadfence();
    if (warp < 8) {
        const int img = warp;              // one warp per image (32 partials)
        const int s = img * 32 + lane;
        double v0 = d_partials[s][0];
        double v1 = d_partials[s][1];
        double v2 = d_partials[s][2];
        double v3 = d_partials[s][3];
#pragma unroll
        for (int off = 16; off > 0; off >>= 1) {
            v0 += __shfl_down_sync(0xffffffffu, v0, off);
            v1 += __shfl_down_sync(0xffffffffu, v1, off);
            v2 += __shfl_down_sync(0xffffffffu, v2, off);
            v3 += __shfl_down_sync(0xffffffffu, v3, off);
        }
        if (lane == 0) {
            const double eps = 1e-6;
            fg[img][0] = v0;                                       // boundary sum
            fg[img][1] = 1.0 - (2.0 * v1 + eps) / (v2 + v3 + eps); // dice term
        }
    }
    __syncthreads();
    if (tid == 0) {
        double bl = 0.0, dl = 0.0;
#pragma unroll
        for (int i = 0; i < BB; ++i) { bl += fg[i][0]; dl += fg[i][1]; }
        dl /= (double)BB;
        bl /= (double)(BB * HH * WW);
        out[0] = (float)(dl + bl);  // ALPHA = BETA = 1
        g_fin = 0;                  // reset for next (graph) replay
        __threadfence();
    }
}

// ---------------------------------------------------------------------------
extern "C" void kernel_launch(void* const* d_in, const int* in_sizes, int n_in,
                              void* d_out, int out_size) {
    const float* pred   = (const float*)d_in[0];
    const float* target = (const float*)d_in[1];
    const int*   fl     = (const int*)d_in[2];
    float* out = (float*)d_out;

    fused<<<NBLK, NTH>>>(pred, target, fl, out);
}